// round 11
// baseline (speedup 1.0000x reference)
#include <cuda_runtime.h>

#define NMAX 100000
#define EMAX 1700000
#define KIN  500
#define HID  32
#define NCLS 40

// ---------------- scratch ----------------
__device__ float g_h1[NMAX * HID];
__device__ float g_h2[NMAX * HID];
__device__ float g_invA[NMAX];
__device__ float g_invB[NMAX];
__device__ int   g_deg[NMAX];
__device__ int   g_rowptr[NMAX + 1];
__device__ int   g_cursor[NMAX];
__device__ int   g_col[EMAX];
__device__ int   g_bsum[256];
__device__ int   g_is64;

typedef unsigned long long ull;

__device__ __forceinline__ ull fma2(ull a, ull b, ull c) {
    ull d;
    asm("fma.rn.f32x2 %0, %1, %2, %3;" : "=l"(d) : "l"(a), "l"(b), "l"(c));
    return d;
}
__device__ __forceinline__ ull dup2(float v) {
    ull r;
    asm("mov.b64 %0, {%1, %1};" : "=l"(r) : "f"(v));
    return r;
}
__device__ __forceinline__ void unp2(ull v, float& lo, float& hi) {
    asm("mov.b64 {%0, %1}, %2;" : "=f"(lo), "=f"(hi) : "l"(v));
}

// ---------------- init: zero degree counters + sniff edge dtype ----------------
__global__ void k_init(const int* __restrict__ w, int n) {
    int i = blockIdx.x * blockDim.x + threadIdx.x;
    if (i < n) g_deg[i] = 0;
    if (blockIdx.x == 0 && threadIdx.x < 32) {
        int v = 0;
        for (int j = threadIdx.x; j < 256; j += 32) v |= w[2 * j + 1];
        #pragma unroll
        for (int o = 16; o; o >>= 1) v |= __shfl_xor_sync(0xffffffffu, v, o);
        if (threadIdx.x == 0) g_is64 = (v == 0) ? 1 : 0;
    }
}

__device__ __forceinline__ int edge_at(const void* ei, long long idx) {
    if (g_is64) return (int)((const long long*)ei)[idx];
    return ((const int*)ei)[idx];
}

// ---------------- GEMM1: h1 = relu(x @ W1 + b1), fused row inv-norm ----------------
// R9 config (128 rows x 32 cols, BK=32, 256 threads, 4x4 thread tile, rows paired
// as f32x2) with ONE change: W staged pre-duplicated as f32x2 in smem, removing
// the 4 mov.b64 dups per k from the inner loop (fma-pipe diet: 12 -> 8 ops/k).
__global__ __launch_bounds__(256) void k_gemm1(const float* __restrict__ x,
                                               const float* __restrict__ W1,
                                               const float* __restrict__ b1,
                                               int n) {
    __shared__ __align__(16) float xs[32 * 130];  // [k][row] transposed, even pad
    __shared__ __align__(16) ull   wt2[32 * 32];  // [k][col], entry = {w, w}

    const int tid = threadIdx.x;
    const int cg  = tid & 7;    // col group: cols cg*4..+3
    const int rg  = tid >> 3;   // row group: rows rg*4..+3 (0..31)
    const int rowBase = blockIdx.x * 128;

    ull a00 = 0, a01 = 0, a02 = 0, a03 = 0;
    ull a10 = 0, a11 = 0, a12 = 0, a13 = 0;

    for (int k0 = 0; k0 < KIN; k0 += 32) {
        // stage W tile [32][32] pre-duplicated, zero-padded past K
        #pragma unroll
        for (int q = 0; q < 4; ++q) {
            int idx = tid + q * 256;          // 0..1023
            int kk = idx >> 5, c = idx & 31;
            float w = 0.f;
            if (k0 + kk < KIN) w = W1[(k0 + kk) * HID + c];
            wt2[idx] = dup2(w);
        }
        // stage x tile transposed, coalesced (8 lanes read 128B of one row)
        #pragma unroll
        for (int q = 0; q < 4; ++q) {
            int r = rg + q * 32;              // staging row 0..127
            int grow = rowBase + r;
            int gk = k0 + cg * 4;
            float4 v = make_float4(0.f, 0.f, 0.f, 0.f);
            if (grow < n && gk < KIN)
                v = *(const float4*)(x + (size_t)grow * KIN + gk);
            xs[(cg * 4 + 0) * 130 + r] = v.x;
            xs[(cg * 4 + 1) * 130 + r] = v.y;
            xs[(cg * 4 + 2) * 130 + r] = v.z;
            xs[(cg * 4 + 3) * 130 + r] = v.w;
        }
        __syncthreads();

        #pragma unroll 16
        for (int kk = 0; kk < 32; ++kk) {
            const ull* wp = wt2 + kk * 32 + cg * 4;
            ull w0 = wp[0], w1 = wp[1], w2 = wp[2], w3 = wp[3];
            ull xa = *(const ull*)(xs + kk * 130 + rg * 4);
            ull xb = *(const ull*)(xs + kk * 130 + rg * 4 + 2);
            a00 = fma2(xa, w0, a00); a01 = fma2(xa, w1, a01);
            a02 = fma2(xa, w2, a02); a03 = fma2(xa, w3, a03);
            a10 = fma2(xb, w0, a10); a11 = fma2(xb, w1, a11);
            a12 = fma2(xb, w2, a12); a13 = fma2(xb, w3, a13);
        }
        __syncthreads();
    }

    // epilogue: bias + relu + store + fused inv-norm (8-lane shuffle over cg)
    float bc[4];
    #pragma unroll
    for (int c = 0; c < 4; ++c) bc[c] = b1[cg * 4 + c];

    float r0[4], r1[4], r2[4], r3[4];
    unp2(a00, r0[0], r1[0]); unp2(a01, r0[1], r1[1]);
    unp2(a02, r0[2], r1[2]); unp2(a03, r0[3], r1[3]);
    unp2(a10, r2[0], r3[0]); unp2(a11, r2[1], r3[1]);
    unp2(a12, r2[2], r3[2]); unp2(a13, r2[3], r3[3]);

    int base = rowBase + rg * 4;
    float* rows[4] = {r0, r1, r2, r3};
    #pragma unroll
    for (int i = 0; i < 4; ++i) {
        int row = base + i;
        float4 o;
        o.x = fmaxf(rows[i][0] + bc[0], 0.f);
        o.y = fmaxf(rows[i][1] + bc[1], 0.f);
        o.z = fmaxf(rows[i][2] + bc[2], 0.f);
        o.w = fmaxf(rows[i][3] + bc[3], 0.f);
        float ss = o.x * o.x + o.y * o.y + o.z * o.z + o.w * o.w;
        ss += __shfl_xor_sync(0xffffffffu, ss, 1);
        ss += __shfl_xor_sync(0xffffffffu, ss, 2);
        ss += __shfl_xor_sync(0xffffffffu, ss, 4);
        if (row < n) {
            *(float4*)(g_h1 + (size_t)row * HID + cg * 4) = o;
            if (cg == 0) g_invA[row] = rsqrtf(ss + 1e-12f);
        }
    }
}

// ---------------- CSR build ----------------
__global__ void k_hist(const void* __restrict__ ei, int E) {
    for (int e = blockIdx.x * blockDim.x + threadIdx.x; e < E;
         e += gridDim.x * blockDim.x) {
        int dst = edge_at(ei, (long long)E + e);
        atomicAdd(&g_deg[dst], 1);
    }
}

__global__ void k_scan1(int n) {
    __shared__ int wsum[32];
    int i = blockIdx.x * 1024 + threadIdx.x;
    int lane = threadIdx.x & 31, warp = threadIdx.x >> 5;
    int v = (i < n) ? g_deg[i] : 0;
    int s = v;
    #pragma unroll
    for (int o = 1; o < 32; o <<= 1) {
        int t = __shfl_up_sync(0xffffffffu, s, o);
        if (lane >= o) s += t;
    }
    if (lane == 31) wsum[warp] = s;
    __syncthreads();
    if (warp == 0) {
        int w = wsum[lane];
        #pragma unroll
        for (int o = 1; o < 32; o <<= 1) {
            int t = __shfl_up_sync(0xffffffffu, w, o);
            if (lane >= o) w += t;
        }
        wsum[lane] = w;
    }
    __syncthreads();
    int pre = (warp > 0) ? wsum[warp - 1] : 0;
    s += pre;
    if (i < n) g_rowptr[i + 1] = s;
    if (threadIdx.x == 1023) g_bsum[blockIdx.x] = s;
}

__global__ void k_scan2(int nb) {
    __shared__ int s[256];
    int t = threadIdx.x;
    int v = (t < nb) ? g_bsum[t] : 0;
    s[t] = v;
    __syncthreads();
    for (int off = 1; off < 256; off <<= 1) {
        int u = (t >= off) ? s[t - off] : 0;
        __syncthreads();
        s[t] += u;
        __syncthreads();
    }
    if (t < nb) g_bsum[t] = (t == 0) ? 0 : s[t - 1];
}

__global__ void k_scan3c(int n) {
    int i = blockIdx.x * blockDim.x + threadIdx.x;
    if (i == 0) { g_rowptr[0] = 0; g_cursor[0] = 0; }
    if (i < n) {
        int f = g_rowptr[i + 1] + g_bsum[i >> 10];
        g_rowptr[i + 1] = f;
        if (i + 1 < n) g_cursor[i + 1] = f;
    }
}

__global__ void k_scatter(const void* __restrict__ ei, int E) {
    for (int e = blockIdx.x * blockDim.x + threadIdx.x; e < E;
         e += gridDim.x * blockDim.x) {
        int src = edge_at(ei, e);
        int dst = edge_at(ei, (long long)E + e);
        int p = atomicAdd(&g_cursor[dst], 1);
        g_col[p] = src;
    }
}

// ---------------- AGNN conv: warp per dst, 4 edge-slots x 8 feat-lanes ----------------
__global__ __launch_bounds__(256) void k_conv(int n, const float* __restrict__ beta_ptr,
                                              int dir, int write_norm) {
    const float* hin  = dir ? g_h2 : g_h1;
    float* hout       = dir ? g_h1 : g_h2;
    const float* ninv = dir ? g_invB : g_invA;

    int wid = (blockIdx.x * blockDim.x + threadIdx.x) >> 5;
    if (wid >= n) return;
    int lane = threadIdx.x & 31;
    int sub = lane >> 3;
    int fid = lane & 7;

    float beta = beta_ptr ? *beta_ptr : 1.0f;
    int dst = wid;
    float4 hd = *(const float4*)(hin + (size_t)dst * HID + fid * 4);
    float cb = beta * ninv[dst];
    int s = g_rowptr[dst], e = g_rowptr[dst + 1];

    float ax = 0.f, ay = 0.f, az = 0.f, aw = 0.f, ssum = 0.f;
    int nit = (e - s + 3) >> 2;
    for (int it = 0; it < nit; ++it) {
        int p = s + it * 4 + sub;
        bool valid = p < e;
        int src = valid ? g_col[p] : dst;
        float4 hs = *(const float4*)(hin + (size_t)src * HID + fid * 4);
        float invs = ninv[src];
        float d = hs.x * hd.x + hs.y * hd.y + hs.z * hd.z + hs.w * hd.w;
        d += __shfl_xor_sync(0xffffffffu, d, 1);
        d += __shfl_xor_sync(0xffffffffu, d, 2);
        d += __shfl_xor_sync(0xffffffffu, d, 4);
        float w = valid ? __expf(cb * invs * d) : 0.f;
        ax = fmaf(w, hs.x, ax);
        ay = fmaf(w, hs.y, ay);
        az = fmaf(w, hs.z, az);
        aw = fmaf(w, hs.w, aw);
        ssum += w;
    }
    ax += __shfl_xor_sync(0xffffffffu, ax, 8);  ax += __shfl_xor_sync(0xffffffffu, ax, 16);
    ay += __shfl_xor_sync(0xffffffffu, ay, 8);  ay += __shfl_xor_sync(0xffffffffu, ay, 16);
    az += __shfl_xor_sync(0xffffffffu, az, 8);  az += __shfl_xor_sync(0xffffffffu, az, 16);
    aw += __shfl_xor_sync(0xffffffffu, aw, 8);  aw += __shfl_xor_sync(0xffffffffu, aw, 16);
    ssum += __shfl_xor_sync(0xffffffffu, ssum, 8);
    ssum += __shfl_xor_sync(0xffffffffu, ssum, 16);

    float r = 1.f / (ssum + 1e-16f);
    float4 o = make_float4(ax * r, ay * r, az * r, aw * r);

    if (write_norm) {
        float ss = o.x * o.x + o.y * o.y + o.z * o.z + o.w * o.w;
        ss += __shfl_xor_sync(0xffffffffu, ss, 1);
        ss += __shfl_xor_sync(0xffffffffu, ss, 2);
        ss += __shfl_xor_sync(0xffffffffu, ss, 4);
        if (lane == 0) g_invB[dst] = rsqrtf(ss + 1e-12f);
    }
    if (sub == 0)
        *(float4*)(hout + (size_t)dst * HID + fid * 4) = o;
}

// ---------------- GEMM2: out = h1 @ W2 + b2 ----------------
__global__ __launch_bounds__(128) void k_gemm2(const float* __restrict__ W2,
                                               const float* __restrict__ b2,
                                               float* __restrict__ out, int n) {
    __shared__ __align__(16) float ws[HID * NCLS];
    __shared__ float bs[NCLS];
    for (int i = threadIdx.x; i < HID * NCLS; i += 128) ws[i] = W2[i];
    if (threadIdx.x < NCLS) bs[threadIdx.x] = b2[threadIdx.x];
    __syncthreads();

    int node = blockIdx.x * blockDim.x + threadIdx.x;
    if (node >= n) return;

    float xr[HID];
    #pragma unroll
    for (int q = 0; q < 8; ++q) {
        float4 v = *(const float4*)(g_h1 + (size_t)node * HID + q * 4);
        xr[q * 4 + 0] = v.x; xr[q * 4 + 1] = v.y;
        xr[q * 4 + 2] = v.z; xr[q * 4 + 3] = v.w;
    }
    float acc[NCLS];
    #pragma unroll
    for (int c = 0; c < NCLS; ++c) acc[c] = bs[c];
    #pragma unroll 8
    for (int k = 0; k < HID; ++k) {
        float xv = xr[k];
        #pragma unroll
        for (int c = 0; c < NCLS; ++c) acc[c] = fmaf(xv, ws[k * NCLS + c], acc[c]);
    }
    #pragma unroll
    for (int q = 0; q < 10; ++q) {
        float4 o = make_float4(acc[q * 4], acc[q * 4 + 1], acc[q * 4 + 2], acc[q * 4 + 3]);
        *(float4*)(out + (size_t)node * NCLS + q * 4) = o;
    }
}

// ---------------- host ----------------
extern "C" void kernel_launch(void* const* d_in, const int* in_sizes, int n_in,
                              void* d_out, int out_size) {
    const float* x = nullptr;
    const float* W1 = nullptr;
    const float* b1 = nullptr;
    const float* W2 = nullptr;
    const float* b2 = nullptr;
    const float* beta2 = nullptr;
    const void* ei = nullptr;
    int xsz = 0, esz = 0;

    for (int i = 0; i < n_in; ++i) {
        int sz = in_sizes[i];
        if (sz == NMAX * KIN)            { x = (const float*)d_in[i]; xsz = sz; }
        else if (sz == KIN * HID)        W1 = (const float*)d_in[i];
        else if (sz == HID)              b1 = (const float*)d_in[i];
        else if (sz == HID * NCLS)       W2 = (const float*)d_in[i];
        else if (sz == NCLS)             b2 = (const float*)d_in[i];
        else if (sz == 1)                beta2 = (const float*)d_in[i];
        else if (sz == 2 * EMAX)         { ei = d_in[i]; esz = sz; }
    }
    if (!x || !W1 || !b1 || !W2 || !b2 || !beta2 || !ei) {
        x = (const float*)d_in[0]; xsz = in_sizes[0];
        W1 = (const float*)d_in[1]; b1 = (const float*)d_in[2];
        W2 = (const float*)d_in[3]; b2 = (const float*)d_in[4];
        beta2 = (const float*)d_in[5];
        ei = d_in[6]; esz = in_sizes[6];
    }

    const int n = xsz / KIN;      // 100000
    const int E = esz / 2;        // 1700000
    const int nb = (n + 1023) / 1024;

    k_init<<<(n + 255) / 256, 256>>>((const int*)ei, n);
    k_gemm1<<<(n + 127) / 128, 256>>>(x, W1, b1, n);

    k_hist<<<2048, 256>>>(ei, E);
    k_scan1<<<nb, 1024>>>(n);
    k_scan2<<<1, 256>>>(nb);
    k_scan3c<<<nb, 1024>>>(n);
    k_scatter<<<2048, 256>>>(ei, E);

    k_conv<<<(n + 7) / 8, 256>>>(n, nullptr, 0, 1);   // prop1: beta=1, h1->h2, write g_invB
    k_conv<<<(n + 7) / 8, 256>>>(n, beta2, 1, 0);     // prop2: beta=beta2, h2->h1

    k_gemm2<<<(n + 127) / 128, 128>>>(W2, b2, (float*)d_out, n);
    (void)out_size;
}

// round 12
// speedup vs baseline: 1.5301x; 1.5301x over previous
#include <cuda_runtime.h>

#define NMAX 100000
#define EMAX 1700000
#define KIN  500
#define HID  32
#define NCLS 40

// ---------------- scratch ----------------
__device__ float g_h1[NMAX * HID];
__device__ float g_h2[NMAX * HID];
__device__ float g_invA[NMAX];
__device__ float g_invB[NMAX];
__device__ int   g_deg[NMAX];
__device__ int   g_rowptr[NMAX + 1];
__device__ int   g_cursor[NMAX];
__device__ int   g_col[EMAX];
__device__ int   g_bsum[256];
__device__ int   g_is64;

typedef unsigned long long ull;

__device__ __forceinline__ ull fma2(ull a, ull b, ull c) {
    ull d;
    asm("fma.rn.f32x2 %0, %1, %2, %3;" : "=l"(d) : "l"(a), "l"(b), "l"(c));
    return d;
}
__device__ __forceinline__ ull dup2(float v) {
    ull r;
    asm("mov.b64 %0, {%1, %1};" : "=l"(r) : "f"(v));
    return r;
}
__device__ __forceinline__ void unp2(ull v, float& lo, float& hi) {
    asm("mov.b64 {%0, %1}, %2;" : "=f"(lo), "=f"(hi) : "l"(v));
}

// ---------------- init: zero degree counters + sniff edge dtype ----------------
__global__ void k_init(const int* __restrict__ w, int n) {
    int i = blockIdx.x * blockDim.x + threadIdx.x;
    if (i < n) g_deg[i] = 0;
    if (blockIdx.x == 0 && threadIdx.x < 32) {
        int v = 0;
        for (int j = threadIdx.x; j < 256; j += 32) v |= w[2 * j + 1];
        #pragma unroll
        for (int o = 16; o; o >>= 1) v |= __shfl_xor_sync(0xffffffffu, v, o);
        if (threadIdx.x == 0) g_is64 = (v == 0) ? 1 : 0;
    }
}

__device__ __forceinline__ int edge_at(const void* ei, long long idx) {
    if (g_is64) return (int)((const long long*)ei)[idx];
    return ((const int*)ei)[idx];
}

// ---------------- GEMM1: h1 = relu(x @ W1 + b1), fused row inv-norm ----------------
// R9 configuration (best, 266.7us total): 128 rows x 32 cols tile, BK=32,
// 256 threads, thread tile 4 rows x 4 cols (rows paired as f32x2), 20.7KB smem.
// wt read as float4 (conflict-free, 4-way broadcast); xs reads 8-way broadcast.
__global__ __launch_bounds__(256) void k_gemm1(const float* __restrict__ x,
                                               const float* __restrict__ W1,
                                               const float* __restrict__ b1,
                                               int n) {
    __shared__ __align__(16) float xs[32 * 130];  // [k][row] transposed, even pad
    __shared__ __align__(16) float wt[32 * 32];   // [k][col]

    const int tid = threadIdx.x;
    const int cg  = tid & 7;    // col group: cols cg*4..+3
    const int rg  = tid >> 3;   // row group: rows rg*4..+3 (0..31)
    const int rowBase = blockIdx.x * 128;

    ull a00 = 0, a01 = 0, a02 = 0, a03 = 0;
    ull a10 = 0, a11 = 0, a12 = 0, a13 = 0;

    for (int k0 = 0; k0 < KIN; k0 += 32) {
        // stage W tile [32][32], zero-padded past K
        #pragma unroll
        for (int q = 0; q < 4; ++q) {
            int idx = tid + q * 256;          // 0..1023
            int kk = idx >> 5, c = idx & 31;
            float w = 0.f;
            if (k0 + kk < KIN) w = W1[(k0 + kk) * HID + c];
            wt[idx] = w;
        }
        // stage x tile transposed, coalesced (8 lanes read 128B of one row)
        #pragma unroll
        for (int q = 0; q < 4; ++q) {
            int r = rg + q * 32;              // staging row 0..127
            int grow = rowBase + r;
            int gk = k0 + cg * 4;
            float4 v = make_float4(0.f, 0.f, 0.f, 0.f);
            if (grow < n && gk < KIN)
                v = *(const float4*)(x + (size_t)grow * KIN + gk);
            xs[(cg * 4 + 0) * 130 + r] = v.x;
            xs[(cg * 4 + 1) * 130 + r] = v.y;
            xs[(cg * 4 + 2) * 130 + r] = v.z;
            xs[(cg * 4 + 3) * 130 + r] = v.w;
        }
        __syncthreads();

        #pragma unroll 16
        for (int kk = 0; kk < 32; ++kk) {
            float4 w4 = *(const float4*)(wt + kk * 32 + cg * 4);
            ull xa = *(const ull*)(xs + kk * 130 + rg * 4);
            ull xb = *(const ull*)(xs + kk * 130 + rg * 4 + 2);
            ull w0 = dup2(w4.x), w1 = dup2(w4.y), w2 = dup2(w4.z), w3 = dup2(w4.w);
            a00 = fma2(xa, w0, a00); a01 = fma2(xa, w1, a01);
            a02 = fma2(xa, w2, a02); a03 = fma2(xa, w3, a03);
            a10 = fma2(xb, w0, a10); a11 = fma2(xb, w1, a11);
            a12 = fma2(xb, w2, a12); a13 = fma2(xb, w3, a13);
        }
        __syncthreads();
    }

    // epilogue: bias + relu + store + fused inv-norm (8-lane shuffle over cg)
    float bc[4];
    #pragma unroll
    for (int c = 0; c < 4; ++c) bc[c] = b1[cg * 4 + c];

    float r0[4], r1[4], r2[4], r3[4];
    unp2(a00, r0[0], r1[0]); unp2(a01, r0[1], r1[1]);
    unp2(a02, r0[2], r1[2]); unp2(a03, r0[3], r1[3]);
    unp2(a10, r2[0], r3[0]); unp2(a11, r2[1], r3[1]);
    unp2(a12, r2[2], r3[2]); unp2(a13, r2[3], r3[3]);

    int base = rowBase + rg * 4;
    float* rows[4] = {r0, r1, r2, r3};
    #pragma unroll
    for (int i = 0; i < 4; ++i) {
        int row = base + i;
        float4 o;
        o.x = fmaxf(rows[i][0] + bc[0], 0.f);
        o.y = fmaxf(rows[i][1] + bc[1], 0.f);
        o.z = fmaxf(rows[i][2] + bc[2], 0.f);
        o.w = fmaxf(rows[i][3] + bc[3], 0.f);
        float ss = o.x * o.x + o.y * o.y + o.z * o.z + o.w * o.w;
        ss += __shfl_xor_sync(0xffffffffu, ss, 1);
        ss += __shfl_xor_sync(0xffffffffu, ss, 2);
        ss += __shfl_xor_sync(0xffffffffu, ss, 4);
        if (row < n) {
            *(float4*)(g_h1 + (size_t)row * HID + cg * 4) = o;
            if (cg == 0) g_invA[row] = rsqrtf(ss + 1e-12f);
        }
    }
}

// ---------------- CSR build ----------------
__global__ void k_hist(const void* __restrict__ ei, int E) {
    for (int e = blockIdx.x * blockDim.x + threadIdx.x; e < E;
         e += gridDim.x * blockDim.x) {
        int dst = edge_at(ei, (long long)E + e);
        atomicAdd(&g_deg[dst], 1);
    }
}

__global__ void k_scan1(int n) {
    __shared__ int wsum[32];
    int i = blockIdx.x * 1024 + threadIdx.x;
    int lane = threadIdx.x & 31, warp = threadIdx.x >> 5;
    int v = (i < n) ? g_deg[i] : 0;
    int s = v;
    #pragma unroll
    for (int o = 1; o < 32; o <<= 1) {
        int t = __shfl_up_sync(0xffffffffu, s, o);
        if (lane >= o) s += t;
    }
    if (lane == 31) wsum[warp] = s;
    __syncthreads();
    if (warp == 0) {
        int w = wsum[lane];
        #pragma unroll
        for (int o = 1; o < 32; o <<= 1) {
            int t = __shfl_up_sync(0xffffffffu, w, o);
            if (lane >= o) w += t;
        }
        wsum[lane] = w;
    }
    __syncthreads();
    int pre = (warp > 0) ? wsum[warp - 1] : 0;
    s += pre;
    if (i < n) g_rowptr[i + 1] = s;
    if (threadIdx.x == 1023) g_bsum[blockIdx.x] = s;
}

__global__ void k_scan2(int nb) {
    __shared__ int s[256];
    int t = threadIdx.x;
    int v = (t < nb) ? g_bsum[t] : 0;
    s[t] = v;
    __syncthreads();
    for (int off = 1; off < 256; off <<= 1) {
        int u = (t >= off) ? s[t - off] : 0;
        __syncthreads();
        s[t] += u;
        __syncthreads();
    }
    if (t < nb) g_bsum[t] = (t == 0) ? 0 : s[t - 1];
}

__global__ void k_scan3c(int n) {
    int i = blockIdx.x * blockDim.x + threadIdx.x;
    if (i == 0) { g_rowptr[0] = 0; g_cursor[0] = 0; }
    if (i < n) {
        int f = g_rowptr[i + 1] + g_bsum[i >> 10];
        g_rowptr[i + 1] = f;
        if (i + 1 < n) g_cursor[i + 1] = f;
    }
}

__global__ void k_scatter(const void* __restrict__ ei, int E) {
    for (int e = blockIdx.x * blockDim.x + threadIdx.x; e < E;
         e += gridDim.x * blockDim.x) {
        int src = edge_at(ei, e);
        int dst = edge_at(ei, (long long)E + e);
        int p = atomicAdd(&g_cursor[dst], 1);
        g_col[p] = src;
    }
}

// ---------------- AGNN conv: warp per dst, 4 edge-slots x 8 feat-lanes ----------------
__global__ __launch_bounds__(256) void k_conv(int n, const float* __restrict__ beta_ptr,
                                              int dir, int write_norm) {
    const float* hin  = dir ? g_h2 : g_h1;
    float* hout       = dir ? g_h1 : g_h2;
    const float* ninv = dir ? g_invB : g_invA;

    int wid = (blockIdx.x * blockDim.x + threadIdx.x) >> 5;
    if (wid >= n) return;
    int lane = threadIdx.x & 31;
    int sub = lane >> 3;
    int fid = lane & 7;

    float beta = beta_ptr ? *beta_ptr : 1.0f;
    int dst = wid;
    float4 hd = *(const float4*)(hin + (size_t)dst * HID + fid * 4);
    float cb = beta * ninv[dst];
    int s = g_rowptr[dst], e = g_rowptr[dst + 1];

    float ax = 0.f, ay = 0.f, az = 0.f, aw = 0.f, ssum = 0.f;
    int nit = (e - s + 3) >> 2;
    for (int it = 0; it < nit; ++it) {
        int p = s + it * 4 + sub;
        bool valid = p < e;
        int src = valid ? g_col[p] : dst;
        float4 hs = *(const float4*)(hin + (size_t)src * HID + fid * 4);
        float invs = ninv[src];
        float d = hs.x * hd.x + hs.y * hd.y + hs.z * hd.z + hs.w * hd.w;
        d += __shfl_xor_sync(0xffffffffu, d, 1);
        d += __shfl_xor_sync(0xffffffffu, d, 2);
        d += __shfl_xor_sync(0xffffffffu, d, 4);
        float w = valid ? __expf(cb * invs * d) : 0.f;
        ax = fmaf(w, hs.x, ax);
        ay = fmaf(w, hs.y, ay);
        az = fmaf(w, hs.z, az);
        aw = fmaf(w, hs.w, aw);
        ssum += w;
    }
    ax += __shfl_xor_sync(0xffffffffu, ax, 8);  ax += __shfl_xor_sync(0xffffffffu, ax, 16);
    ay += __shfl_xor_sync(0xffffffffu, ay, 8);  ay += __shfl_xor_sync(0xffffffffu, ay, 16);
    az += __shfl_xor_sync(0xffffffffu, az, 8);  az += __shfl_xor_sync(0xffffffffu, az, 16);
    aw += __shfl_xor_sync(0xffffffffu, aw, 8);  aw += __shfl_xor_sync(0xffffffffu, aw, 16);
    ssum += __shfl_xor_sync(0xffffffffu, ssum, 8);
    ssum += __shfl_xor_sync(0xffffffffu, ssum, 16);

    float r = 1.f / (ssum + 1e-16f);
    float4 o = make_float4(ax * r, ay * r, az * r, aw * r);

    if (write_norm) {
        float ss = o.x * o.x + o.y * o.y + o.z * o.z + o.w * o.w;
        ss += __shfl_xor_sync(0xffffffffu, ss, 1);
        ss += __shfl_xor_sync(0xffffffffu, ss, 2);
        ss += __shfl_xor_sync(0xffffffffu, ss, 4);
        if (lane == 0) g_invB[dst] = rsqrtf(ss + 1e-12f);
    }
    if (sub == 0)
        *(float4*)(hout + (size_t)dst * HID + fid * 4) = o;
}

// ---------------- GEMM2: out = h1 @ W2 + b2 ----------------
__global__ __launch_bounds__(128) void k_gemm2(const float* __restrict__ W2,
                                               const float* __restrict__ b2,
                                               float* __restrict__ out, int n) {
    __shared__ __align__(16) float ws[HID * NCLS];
    __shared__ float bs[NCLS];
    for (int i = threadIdx.x; i < HID * NCLS; i += 128) ws[i] = W2[i];
    if (threadIdx.x < NCLS) bs[threadIdx.x] = b2[threadIdx.x];
    __syncthreads();

    int node = blockIdx.x * blockDim.x + threadIdx.x;
    if (node >= n) return;

    float xr[HID];
    #pragma unroll
    for (int q = 0; q < 8; ++q) {
        float4 v = *(const float4*)(g_h1 + (size_t)node * HID + q * 4);
        xr[q * 4 + 0] = v.x; xr[q * 4 + 1] = v.y;
        xr[q * 4 + 2] = v.z; xr[q * 4 + 3] = v.w;
    }
    float acc[NCLS];
    #pragma unroll
    for (int c = 0; c < NCLS; ++c) acc[c] = bs[c];
    #pragma unroll 8
    for (int k = 0; k < HID; ++k) {
        float xv = xr[k];
        #pragma unroll
        for (int c = 0; c < NCLS; ++c) acc[c] = fmaf(xv, ws[k * NCLS + c], acc[c]);
    }
    #pragma unroll
    for (int q = 0; q < 10; ++q) {
        float4 o = make_float4(acc[q * 4], acc[q * 4 + 1], acc[q * 4 + 2], acc[q * 4 + 3]);
        *(float4*)(out + (size_t)node * NCLS + q * 4) = o;
    }
}

// ---------------- host ----------------
extern "C" void kernel_launch(void* const* d_in, const int* in_sizes, int n_in,
                              void* d_out, int out_size) {
    const float* x = nullptr;
    const float* W1 = nullptr;
    const float* b1 = nullptr;
    const float* W2 = nullptr;
    const float* b2 = nullptr;
    const float* beta2 = nullptr;
    const void* ei = nullptr;
    int xsz = 0, esz = 0;

    for (int i = 0; i < n_in; ++i) {
        int sz = in_sizes[i];
        if (sz == NMAX * KIN)            { x = (const float*)d_in[i]; xsz = sz; }
        else if (sz == KIN * HID)        W1 = (const float*)d_in[i];
        else if (sz == HID)              b1 = (const float*)d_in[i];
        else if (sz == HID * NCLS)       W2 = (const float*)d_in[i];
        else if (sz == NCLS)             b2 = (const float*)d_in[i];
        else if (sz == 1)                beta2 = (const float*)d_in[i];
        else if (sz == 2 * EMAX)         { ei = d_in[i]; esz = sz; }
    }
    if (!x || !W1 || !b1 || !W2 || !b2 || !beta2 || !ei) {
        x = (const float*)d_in[0]; xsz = in_sizes[0];
        W1 = (const float*)d_in[1]; b1 = (const float*)d_in[2];
        W2 = (const float*)d_in[3]; b2 = (const float*)d_in[4];
        beta2 = (const float*)d_in[5];
        ei = d_in[6]; esz = in_sizes[6];
    }

    const int n = xsz / KIN;      // 100000
    const int E = esz / 2;        // 1700000
    const int nb = (n + 1023) / 1024;

    k_init<<<(n + 255) / 256, 256>>>((const int*)ei, n);
    k_gemm1<<<(n + 127) / 128, 256>>>(x, W1, b1, n);

    k_hist<<<2048, 256>>>(ei, E);
    k_scan1<<<nb, 1024>>>(n);
    k_scan2<<<1, 256>>>(nb);
    k_scan3c<<<nb, 1024>>>(n);
    k_scatter<<<2048, 256>>>(ei, E);

    k_conv<<<(n + 7) / 8, 256>>>(n, nullptr, 0, 1);   // prop1: beta=1, h1->h2, write g_invB
    k_conv<<<(n + 7) / 8, 256>>>(n, beta2, 1, 0);     // prop2: beta=beta2, h2->h1

    k_gemm2<<<(n + 127) / 128, 128>>>(W2, b2, (float*)d_out, n);
    (void)out_size;
}

// round 15
// speedup vs baseline: 1.7146x; 1.1206x over previous
#include <cuda_runtime.h>

#define NMAX 100000
#define EMAX 1700000
#define KIN  500
#define HID  32
#define NCLS 40

// ---------------- scratch ----------------
__device__ float g_h1[NMAX * HID];
__device__ float g_h2[NMAX * HID];
__device__ float g_invA[NMAX];
__device__ float g_invB[NMAX];
__device__ int   g_deg[NMAX];
__device__ int   g_rowptr[NMAX + 1];
__device__ int   g_cursor[NMAX];
__device__ int   g_col[EMAX];
__device__ int   g_bsum[256];
__device__ int   g_is64;

typedef unsigned long long ull;
typedef unsigned int uint;

// ---------------- init: zero degree counters + sniff edge dtype ----------------
__global__ void k_init(const int* __restrict__ w, int n) {
    int i = blockIdx.x * blockDim.x + threadIdx.x;
    if (i < n) g_deg[i] = 0;
    if (blockIdx.x == 0 && threadIdx.x < 32) {
        int v = 0;
        for (int j = threadIdx.x; j < 256; j += 32) v |= w[2 * j + 1];
        #pragma unroll
        for (int o = 16; o; o >>= 1) v |= __shfl_xor_sync(0xffffffffu, v, o);
        if (threadIdx.x == 0) g_is64 = (v == 0) ? 1 : 0;
    }
}

__device__ __forceinline__ int edge_at(const void* ei, long long idx) {
    if (g_is64) return (int)((const long long*)ei)[idx];
    return ((const int*)ei)[idx];
}

// ---------------- tensor-core helpers ----------------
__device__ __forceinline__ uint s2u(const void* p) {
    uint a;
    asm("{ .reg .u64 t; cvta.to.shared.u64 t, %1; cvt.u32.u64 %0, t; }"
        : "=r"(a) : "l"(p));
    return a;
}
// split a pair of fp32 into bf16x2 hi (RN) + bf16x2 residual (RN)
__device__ __forceinline__ void cvt_split(float a, float b, uint& hp, uint& lp) {
    uint h;
    asm("cvt.rn.bf16x2.f32 %0, %1, %2;" : "=r"(h) : "f"(b), "f"(a)); // {hi:b, lo:a}
    float ha = __uint_as_float(h << 16);
    float hb = __uint_as_float(h & 0xffff0000u);
    float la = a - ha, lb = b - hb;   // exact (Sterbenz split)
    asm("cvt.rn.bf16x2.f32 %0, %1, %2;" : "=r"(lp) : "f"(lb), "f"(la));
    hp = h;
}
#define LDSMX4(r0, r1, r2, r3, addr) \
    asm volatile("ldmatrix.sync.aligned.m8n8.x4.shared.b16 {%0,%1,%2,%3}, [%4];" \
                 : "=r"(r0), "=r"(r1), "=r"(r2), "=r"(r3) : "r"(addr))
#define LDSMX4T(r0, r1, r2, r3, addr) \
    asm volatile("ldmatrix.sync.aligned.m8n8.x4.trans.shared.b16 {%0,%1,%2,%3}, [%4];" \
                 : "=r"(r0), "=r"(r1), "=r"(r2), "=r"(r3) : "r"(addr))
#define MMA16816(d, a0, a1, a2, a3, b0, b1) \
    asm volatile("mma.sync.aligned.m16n8k16.row.col.f32.bf16.bf16.f32 " \
                 "{%0,%1,%2,%3},{%4,%5,%6,%7},{%8,%9},{%0,%1,%2,%3};" \
                 : "+f"(d[0]), "+f"(d[1]), "+f"(d[2]), "+f"(d[3]) \
                 : "r"(a0), "r"(a1), "r"(a2), "r"(a3), "r"(b0), "r"(b1))

// ---------------- GEMM1 (tensor cores, bf16-split): h1 = relu(x@W1+b1), fused inv-norm ----
// Block 256 thr = 8 warps; tile 128 rows x 32 cols; BK=32 (K 500 zero-padded to 512).
// Per warp: 16 rows x 32 cols. D = Ah*Bh + Ah*Bl + Al*Bh (xl*wl dropped, ~1e-5 rel).
// smem pitch 40 bf16 (80B) -> ldmatrix conflict-free (r*20 mod 32 covers all banks).
__global__ __launch_bounds__(256) void k_gemm1(const float* __restrict__ x,
                                               const float* __restrict__ W1,
                                               const float* __restrict__ b1,
                                               int n) {
    __shared__ __align__(16) uint Ah[128 * 20];
    __shared__ __align__(16) uint Al[128 * 20];
    __shared__ __align__(16) uint Bh[32 * 20];
    __shared__ __align__(16) uint Bl[32 * 20];

    const int tid = threadIdx.x;
    const int lane = tid & 31, w = tid >> 5;
    const int rowBase = blockIdx.x * 128;

    float d[4][4] = {{0.f, 0.f, 0.f, 0.f}, {0.f, 0.f, 0.f, 0.f},
                     {0.f, 0.f, 0.f, 0.f}, {0.f, 0.f, 0.f, 0.f}};

    // ldmatrix lane addresses (bytes)
    const int a_row = w * 16 + (lane & 7) + ((lane >> 3) & 1) * 8;
    const int a_k8  = (lane >> 4) * 8;
    const uint aAddrH = s2u(Ah) + (uint)(a_row * 40 + a_k8) * 2;
    const uint aAddrL = s2u(Al) + (uint)(a_row * 40 + a_k8) * 2;
    const int b_k = (lane & 7) + ((lane >> 3) & 1) * 8;
    const int b_n = (lane >> 4) * 8;
    const uint bAddrH = s2u(Bh) + (uint)(b_k * 40 + b_n) * 2;
    const uint bAddrL = s2u(Bl) + (uint)(b_k * 40 + b_n) * 2;

    for (int t = 0; t < 16; ++t) {
        const int k0 = t * 32;
        // stage B tile [32k][32n]
        {
            int kk = tid >> 3, c = (tid & 7) * 4;
            float4 v = make_float4(0.f, 0.f, 0.f, 0.f);
            if (k0 + kk < KIN) v = *(const float4*)(W1 + (size_t)(k0 + kk) * HID + c);
            uint h01, l01, h23, l23;
            cvt_split(v.x, v.y, h01, l01);
            cvt_split(v.z, v.w, h23, l23);
            int bi = kk * 20 + (tid & 7) * 2;
            Bh[bi] = h01; Bh[bi + 1] = h23;
            Bl[bi] = l01; Bl[bi + 1] = l23;
        }
        // stage A tile [128r][32k]  (flat float4 mapping, coalesced)
        #pragma unroll
        for (int q = 0; q < 4; ++q) {
            int f4 = tid + q * 256;            // 0..1023
            int row = f4 >> 3, c4 = f4 & 7;
            int gk = k0 + c4 * 4;
            float4 v = make_float4(0.f, 0.f, 0.f, 0.f);
            if ((rowBase + row) < n && gk < KIN)
                v = *(const float4*)(x + (size_t)(rowBase + row) * KIN + gk);
            uint h01, l01, h23, l23;
            cvt_split(v.x, v.y, h01, l01);
            cvt_split(v.z, v.w, h23, l23);
            int ai = row * 20 + c4 * 2;
            Ah[ai] = h01; Ah[ai + 1] = h23;
            Al[ai] = l01; Al[ai + 1] = l23;
        }
        __syncthreads();

        #pragma unroll
        for (int ks = 0; ks < 32; ks += 16) {
            uint ah0, ah1, ah2, ah3, al0, al1, al2, al3;
            LDSMX4(ah0, ah1, ah2, ah3, aAddrH + ks * 2);
            LDSMX4(al0, al1, al2, al3, aAddrL + ks * 2);
            #pragma unroll
            for (int j2 = 0; j2 < 2; ++j2) {
                uint off = (uint)(ks * 40 + j2 * 16) * 2;
                uint bh0, bh1, bh2, bh3, bl0, bl1, bl2, bl3;
                LDSMX4T(bh0, bh1, bh2, bh3, bAddrH + off);
                LDSMX4T(bl0, bl1, bl2, bl3, bAddrL + off);
                MMA16816(d[2 * j2],     ah0, ah1, ah2, ah3, bh0, bh1);
                MMA16816(d[2 * j2],     ah0, ah1, ah2, ah3, bl0, bl1);
                MMA16816(d[2 * j2],     al0, al1, al2, al3, bh0, bh1);
                MMA16816(d[2 * j2 + 1], ah0, ah1, ah2, ah3, bh2, bh3);
                MMA16816(d[2 * j2 + 1], ah0, ah1, ah2, ah3, bl2, bl3);
                MMA16816(d[2 * j2 + 1], al0, al1, al2, al3, bh2, bh3);
            }
        }
        __syncthreads();
    }

    // epilogue: bias + relu + store + fused inv-norm
    const int r0 = w * 16 + (lane >> 2);
    const int gr0 = rowBase + r0, gr1 = gr0 + 8;
    const int cbase = (lane & 3) * 2;
    float ss0 = 0.f, ss1 = 0.f;
    #pragma unroll
    for (int j = 0; j < 4; ++j) {
        int c = j * 8 + cbase;
        float bb0 = b1[c], bb1 = b1[c + 1];
        float o0 = fmaxf(d[j][0] + bb0, 0.f), o1 = fmaxf(d[j][1] + bb1, 0.f);
        float o2 = fmaxf(d[j][2] + bb0, 0.f), o3 = fmaxf(d[j][3] + bb1, 0.f);
        ss0 += o0 * o0 + o1 * o1;
        ss1 += o2 * o2 + o3 * o3;
        if (gr0 < n) *(float2*)(g_h1 + (size_t)gr0 * HID + c) = make_float2(o0, o1);
        if (gr1 < n) *(float2*)(g_h1 + (size_t)gr1 * HID + c) = make_float2(o2, o3);
    }
    ss0 += __shfl_xor_sync(0xffffffffu, ss0, 1);
    ss0 += __shfl_xor_sync(0xffffffffu, ss0, 2);
    ss1 += __shfl_xor_sync(0xffffffffu, ss1, 1);
    ss1 += __shfl_xor_sync(0xffffffffu, ss1, 2);
    if ((lane & 3) == 0) {
        if (gr0 < n) g_invA[gr0] = rsqrtf(ss0 + 1e-12f);
        if (gr1 < n) g_invA[gr1] = rsqrtf(ss1 + 1e-12f);
    }
}

// ---------------- CSR build ----------------
__global__ void k_hist(const void* __restrict__ ei, int E) {
    for (int e = blockIdx.x * blockDim.x + threadIdx.x; e < E;
         e += gridDim.x * blockDim.x) {
        int dst = edge_at(ei, (long long)E + e);
        atomicAdd(&g_deg[dst], 1);
    }
}

__global__ void k_scan1(int n) {
    __shared__ int wsum[32];
    int i = blockIdx.x * 1024 + threadIdx.x;
    int lane = threadIdx.x & 31, warp = threadIdx.x >> 5;
    int v = (i < n) ? g_deg[i] : 0;
    int s = v;
    #pragma unroll
    for (int o = 1; o < 32; o <<= 1) {
        int t = __shfl_up_sync(0xffffffffu, s, o);
        if (lane >= o) s += t;
    }
    if (lane == 31) wsum[warp] = s;
    __syncthreads();
    if (warp == 0) {
        int w = wsum[lane];
        #pragma unroll
        for (int o = 1; o < 32; o <<= 1) {
            int t = __shfl_up_sync(0xffffffffu, w, o);
            if (lane >= o) w += t;
        }
        wsum[lane] = w;
    }
    __syncthreads();
    int pre = (warp > 0) ? wsum[warp - 1] : 0;
    s += pre;
    if (i < n) g_rowptr[i + 1] = s;
    if (threadIdx.x == 1023) g_bsum[blockIdx.x] = s;
}

__global__ void k_scan2(int nb) {
    __shared__ int s[256];
    int t = threadIdx.x;
    int v = (t < nb) ? g_bsum[t] : 0;
    s[t] = v;
    __syncthreads();
    for (int off = 1; off < 256; off <<= 1) {
        int u = (t >= off) ? s[t - off] : 0;
        __syncthreads();
        s[t] += u;
        __syncthreads();
    }
    if (t < nb) g_bsum[t] = (t == 0) ? 0 : s[t - 1];
}

__global__ void k_scan3c(int n) {
    int i = blockIdx.x * blockDim.x + threadIdx.x;
    if (i == 0) { g_rowptr[0] = 0; g_cursor[0] = 0; }
    if (i < n) {
        int f = g_rowptr[i + 1] + g_bsum[i >> 10];
        g_rowptr[i + 1] = f;
        if (i + 1 < n) g_cursor[i + 1] = f;
    }
}

__global__ void k_scatter(const void* __restrict__ ei, int E) {
    for (int e = blockIdx.x * blockDim.x + threadIdx.x; e < E;
         e += gridDim.x * blockDim.x) {
        int src = edge_at(ei, e);
        int dst = edge_at(ei, (long long)E + e);
        int p = atomicAdd(&g_cursor[dst], 1);
        g_col[p] = src;
    }
}

// ---------------- AGNN conv: warp per dst, 4 edge-slots x 8 feat-lanes ----------------
__global__ __launch_bounds__(256) void k_conv(int n, const float* __restrict__ beta_ptr,
                                              int dir, int write_norm) {
    const float* hin  = dir ? g_h2 : g_h1;
    float* hout       = dir ? g_h1 : g_h2;
    const float* ninv = dir ? g_invB : g_invA;

    int wid = (blockIdx.x * blockDim.x + threadIdx.x) >> 5;
    if (wid >= n) return;
    int lane = threadIdx.x & 31;
    int sub = lane >> 3;
    int fid = lane & 7;

    float beta = beta_ptr ? *beta_ptr : 1.0f;
    int dst = wid;
    float4 hd = *(const float4*)(hin + (size_t)dst * HID + fid * 4);
    float cb = beta * ninv[dst];
    int s = g_rowptr[dst], e = g_rowptr[dst + 1];

    float ax = 0.f, ay = 0.f, az = 0.f, aw = 0.f, ssum = 0.f;
    int nit = (e - s + 3) >> 2;
    for (int it = 0; it < nit; ++it) {
        int p = s + it * 4 + sub;
        bool valid = p < e;
        int src = valid ? g_col[p] : dst;
        float4 hs = *(const float4*)(hin + (size_t)src * HID + fid * 4);
        float invs = ninv[src];
        float d = hs.x * hd.x + hs.y * hd.y + hs.z * hd.z + hs.w * hd.w;
        d += __shfl_xor_sync(0xffffffffu, d, 1);
        d += __shfl_xor_sync(0xffffffffu, d, 2);
        d += __shfl_xor_sync(0xffffffffu, d, 4);
        float w = valid ? __expf(cb * invs * d) : 0.f;
        ax = fmaf(w, hs.x, ax);
        ay = fmaf(w, hs.y, ay);
        az = fmaf(w, hs.z, az);
        aw = fmaf(w, hs.w, aw);
        ssum += w;
    }
    ax += __shfl_xor_sync(0xffffffffu, ax, 8);  ax += __shfl_xor_sync(0xffffffffu, ax, 16);
    ay += __shfl_xor_sync(0xffffffffu, ay, 8);  ay += __shfl_xor_sync(0xffffffffu, ay, 16);
    az += __shfl_xor_sync(0xffffffffu, az, 8);  az += __shfl_xor_sync(0xffffffffu, az, 16);
    aw += __shfl_xor_sync(0xffffffffu, aw, 8);  aw += __shfl_xor_sync(0xffffffffu, aw, 16);
    ssum += __shfl_xor_sync(0xffffffffu, ssum, 8);
    ssum += __shfl_xor_sync(0xffffffffu, ssum, 16);

    float r = 1.f / (ssum + 1e-16f);
    float4 o = make_float4(ax * r, ay * r, az * r, aw * r);

    if (write_norm) {
        float ss = o.x * o.x + o.y * o.y + o.z * o.z + o.w * o.w;
        ss += __shfl_xor_sync(0xffffffffu, ss, 1);
        ss += __shfl_xor_sync(0xffffffffu, ss, 2);
        ss += __shfl_xor_sync(0xffffffffu, ss, 4);
        if (lane == 0) g_invB[dst] = rsqrtf(ss + 1e-12f);
    }
    if (sub == 0)
        *(float4*)(hout + (size_t)dst * HID + fid * 4) = o;
}

// ---------------- GEMM2: out = h1 @ W2 + b2 ----------------
__global__ __launch_bounds__(128) void k_gemm2(const float* __restrict__ W2,
                                               const float* __restrict__ b2,
                                               float* __restrict__ out, int n) {
    __shared__ __align__(16) float ws[HID * NCLS];
    __shared__ float bs[NCLS];
    for (int i = threadIdx.x; i < HID * NCLS; i += 128) ws[i] = W2[i];
    if (threadIdx.x < NCLS) bs[threadIdx.x] = b2[threadIdx.x];
    __syncthreads();

    int node = blockIdx.x * blockDim.x + threadIdx.x;
    if (node >= n) return;

    float xr[HID];
    #pragma unroll
    for (int q = 0; q < 8; ++q) {
        float4 v = *(const float4*)(g_h1 + (size_t)node * HID + q * 4);
        xr[q * 4 + 0] = v.x; xr[q * 4 + 1] = v.y;
        xr[q * 4 + 2] = v.z; xr[q * 4 + 3] = v.w;
    }
    float acc[NCLS];
    #pragma unroll
    for (int c = 0; c < NCLS; ++c) acc[c] = bs[c];
    #pragma unroll 8
    for (int k = 0; k < HID; ++k) {
        float xv = xr[k];
        #pragma unroll
        for (int c = 0; c < NCLS; ++c) acc[c] = fmaf(xv, ws[k * NCLS + c], acc[c]);
    }
    #pragma unroll
    for (int q = 0; q < 10; ++q) {
        float4 o = make_float4(acc[q * 4], acc[q * 4 + 1], acc[q * 4 + 2], acc[q * 4 + 3]);
        *(float4*)(out + (size_t)node * NCLS + q * 4) = o;
    }
}

// ---------------- host ----------------
extern "C" void kernel_launch(void* const* d_in, const int* in_sizes, int n_in,
                              void* d_out, int out_size) {
    const float* x = nullptr;
    const float* W1 = nullptr;
    const float* b1 = nullptr;
    const float* W2 = nullptr;
    const float* b2 = nullptr;
    const float* beta2 = nullptr;
    const void* ei = nullptr;
    int xsz = 0, esz = 0;

    for (int i = 0; i < n_in; ++i) {
        int sz = in_sizes[i];
        if (sz == NMAX * KIN)            { x = (const float*)d_in[i]; xsz = sz; }
        else if (sz == KIN * HID)        W1 = (const float*)d_in[i];
        else if (sz == HID)              b1 = (const float*)d_in[i];
        else if (sz == HID * NCLS)       W2 = (const float*)d_in[i];
        else if (sz == NCLS)             b2 = (const float*)d_in[i];
        else if (sz == 1)                beta2 = (const float*)d_in[i];
        else if (sz == 2 * EMAX)         { ei = d_in[i]; esz = sz; }
    }
    if (!x || !W1 || !b1 || !W2 || !b2 || !beta2 || !ei) {
        x = (const float*)d_in[0]; xsz = in_sizes[0];
        W1 = (const float*)d_in[1]; b1 = (const float*)d_in[2];
        W2 = (const float*)d_in[3]; b2 = (const float*)d_in[4];
        beta2 = (const float*)d_in[5];
        ei = d_in[6]; esz = in_sizes[6];
    }

    const int n = xsz / KIN;      // 100000
    const int E = esz / 2;        // 1700000
    const int nb = (n + 1023) / 1024;

    k_init<<<(n + 255) / 256, 256>>>((const int*)ei, n);
    k_gemm1<<<(n + 127) / 128, 256>>>(x, W1, b1, n);

    k_hist<<<2048, 256>>>(ei, E);
    k_scan1<<<nb, 1024>>>(n);
    k_scan2<<<1, 256>>>(nb);
    k_scan3c<<<nb, 1024>>>(n);
    k_scatter<<<2048, 256>>>(ei, E);

    k_conv<<<(n + 7) / 8, 256>>>(n, nullptr, 0, 1);   // prop1: beta=1, h1->h2, write g_invB
    k_conv<<<(n + 7) / 8, 256>>>(n, beta2, 1, 0);     // prop2: beta=beta2, h2->h1

    k_gemm2<<<(n + 127) / 128, 128>>>(W2, b2, (float*)d_out, n);
    (void)out_size;
}

// round 17
// speedup vs baseline: 1.7779x; 1.0369x over previous
#include <cuda_runtime.h>

#define NMAX 100000
#define EMAX 1700000
#define KIN  500
#define HID  32
#define NCLS 40
#define NB_HIST 2048

// ---------------- scratch ----------------
__device__ float g_h1[NMAX * HID];
__device__ float g_h2[NMAX * HID];
__device__ float g_invA[NMAX];
__device__ float g_invB[NMAX];
__device__ int   g_deg[NMAX];
__device__ int   g_rowptr[NMAX + 1];
__device__ int   g_cursor[NMAX];
__device__ int   g_col[EMAX];
__device__ int   g_dst32[EMAX];
__device__ int   g_bsum[256];
__device__ int   g_is64;

typedef unsigned long long ull;
typedef unsigned int uint;

// ---------------- init: zero degree counters + sniff edge dtype ----------------
__global__ void k_init(const int* __restrict__ w, int n) {
    int i = blockIdx.x * blockDim.x + threadIdx.x;
    if (i < n) g_deg[i] = 0;
    if (blockIdx.x == 0 && threadIdx.x < 32) {
        int v = 0;
        for (int j = threadIdx.x; j < 256; j += 32) v |= w[2 * j + 1];
        #pragma unroll
        for (int o = 16; o; o >>= 1) v |= __shfl_xor_sync(0xffffffffu, v, o);
        if (threadIdx.x == 0) g_is64 = (v == 0) ? 1 : 0;
    }
}

__device__ __forceinline__ int edge_at(const void* ei, long long idx) {
    if (g_is64) return (int)((const long long*)ei)[idx];
    return ((const int*)ei)[idx];
}

// ---------------- tensor-core helpers ----------------
__device__ __forceinline__ uint s2u(const void* p) {
    uint a;
    asm("{ .reg .u64 t; cvta.to.shared.u64 t, %1; cvt.u32.u64 %0, t; }"
        : "=r"(a) : "l"(p));
    return a;
}
// split a pair of fp32 into bf16x2 hi (RN) + bf16x2 residual (RN)
__device__ __forceinline__ void cvt_split(float a, float b, uint& hp, uint& lp) {
    uint h;
    asm("cvt.rn.bf16x2.f32 %0, %1, %2;" : "=r"(h) : "f"(b), "f"(a)); // {hi:b, lo:a}
    float ha = __uint_as_float(h << 16);
    float hb = __uint_as_float(h & 0xffff0000u);
    float la = a - ha, lb = b - hb;
    asm("cvt.rn.bf16x2.f32 %0, %1, %2;" : "=r"(lp) : "f"(lb), "f"(la));
    hp = h;
}
#define LDSMX4(r0, r1, r2, r3, addr) \
    asm volatile("ldmatrix.sync.aligned.m8n8.x4.shared.b16 {%0,%1,%2,%3}, [%4];" \
                 : "=r"(r0), "=r"(r1), "=r"(r2), "=r"(r3) : "r"(addr))
#define LDSMX4T(r0, r1, r2, r3, addr) \
    asm volatile("ldmatrix.sync.aligned.m8n8.x4.trans.shared.b16 {%0,%1,%2,%3}, [%4];" \
                 : "=r"(r0), "=r"(r1), "=r"(r2), "=r"(r3) : "r"(addr))
#define MMA16816(d, a0, a1, a2, a3, b0, b1) \
    asm volatile("mma.sync.aligned.m16n8k16.row.col.f32.bf16.bf16.f32 " \
                 "{%0,%1,%2,%3},{%4,%5,%6,%7},{%8,%9},{%0,%1,%2,%3};" \
                 : "+f"(d[0]), "+f"(d[1]), "+f"(d[2]), "+f"(d[3]) \
                 : "r"(a0), "r"(a1), "r"(a2), "r"(a3), "r"(b0), "r"(b1))

// ---------------- fused GEMM1 + hist ----------------
// Blocks [0, nbG): tensor-core GEMM1 h1 = relu(x@W1+b1) with fused inv-norm.
// Blocks [nbG, nbG+NB_HIST): edge histogram (atomicAdd g_deg) + save dst as int32.
// The two roles touch disjoint state -> safe in one launch; they overlap on
// complementary pipes (tensor/LSU vs L2-atomic).
__global__ __launch_bounds__(256) void k_g1h(const float* __restrict__ x,
                                             const float* __restrict__ W1,
                                             const float* __restrict__ b1,
                                             int n, int nbG,
                                             const void* __restrict__ ei, int E) {
    // ---- hist role ----
    if ((int)blockIdx.x >= nbG) {
        int b = blockIdx.x - nbG;
        for (int e = b * 256 + threadIdx.x; e < E; e += NB_HIST * 256) {
            int dst = edge_at(ei, (long long)E + e);
            g_dst32[e] = dst;
            atomicAdd(&g_deg[dst], 1);
        }
        return;
    }

    // ---- GEMM1 role ----
    __shared__ __align__(16) uint Ah[128 * 20];
    __shared__ __align__(16) uint Al[128 * 20];
    __shared__ __align__(16) uint Bh[32 * 20];
    __shared__ __align__(16) uint Bl[32 * 20];

    const int tid = threadIdx.x;
    const int lane = tid & 31, w = tid >> 5;
    const int rowBase = blockIdx.x * 128;

    float d[4][4] = {{0.f, 0.f, 0.f, 0.f}, {0.f, 0.f, 0.f, 0.f},
                     {0.f, 0.f, 0.f, 0.f}, {0.f, 0.f, 0.f, 0.f}};

    const int a_row = w * 16 + (lane & 7) + ((lane >> 3) & 1) * 8;
    const int a_k8  = (lane >> 4) * 8;
    const uint aAddrH = s2u(Ah) + (uint)(a_row * 40 + a_k8) * 2;
    const uint aAddrL = s2u(Al) + (uint)(a_row * 40 + a_k8) * 2;
    const int b_k = (lane & 7) + ((lane >> 3) & 1) * 8;
    const int b_n = (lane >> 4) * 8;
    const uint bAddrH = s2u(Bh) + (uint)(b_k * 40 + b_n) * 2;
    const uint bAddrL = s2u(Bl) + (uint)(b_k * 40 + b_n) * 2;

    for (int t = 0; t < 16; ++t) {
        const int k0 = t * 32;
        {
            int kk = tid >> 3, c = (tid & 7) * 4;
            float4 v = make_float4(0.f, 0.f, 0.f, 0.f);
            if (k0 + kk < KIN) v = *(const float4*)(W1 + (size_t)(k0 + kk) * HID + c);
            uint h01, l01, h23, l23;
            cvt_split(v.x, v.y, h01, l01);
            cvt_split(v.z, v.w, h23, l23);
            int bi = kk * 20 + (tid & 7) * 2;
            Bh[bi] = h01; Bh[bi + 1] = h23;
            Bl[bi] = l01; Bl[bi + 1] = l23;
        }
        #pragma unroll
        for (int q = 0; q < 4; ++q) {
            int f4 = tid + q * 256;
            int row = f4 >> 3, c4 = f4 & 7;
            int gk = k0 + c4 * 4;
            float4 v = make_float4(0.f, 0.f, 0.f, 0.f);
            if ((rowBase + row) < n && gk < KIN)
                v = *(const float4*)(x + (size_t)(rowBase + row) * KIN + gk);
            uint h01, l01, h23, l23;
            cvt_split(v.x, v.y, h01, l01);
            cvt_split(v.z, v.w, h23, l23);
            int ai = row * 20 + c4 * 2;
            Ah[ai] = h01; Ah[ai + 1] = h23;
            Al[ai] = l01; Al[ai + 1] = l23;
        }
        __syncthreads();

        #pragma unroll
        for (int ks = 0; ks < 32; ks += 16) {
            uint ah0, ah1, ah2, ah3, al0, al1, al2, al3;
            LDSMX4(ah0, ah1, ah2, ah3, aAddrH + ks * 2);
            LDSMX4(al0, al1, al2, al3, aAddrL + ks * 2);
            #pragma unroll
            for (int j2 = 0; j2 < 2; ++j2) {
                uint off = (uint)(ks * 40 + j2 * 16) * 2;
                uint bh0, bh1, bh2, bh3, bl0, bl1, bl2, bl3;
                LDSMX4T(bh0, bh1, bh2, bh3, bAddrH + off);
                LDSMX4T(bl0, bl1, bl2, bl3, bAddrL + off);
                MMA16816(d[2 * j2],     ah0, ah1, ah2, ah3, bh0, bh1);
                MMA16816(d[2 * j2],     ah0, ah1, ah2, ah3, bl0, bl1);
                MMA16816(d[2 * j2],     al0, al1, al2, al3, bh0, bh1);
                MMA16816(d[2 * j2 + 1], ah0, ah1, ah2, ah3, bh2, bh3);
                MMA16816(d[2 * j2 + 1], ah0, ah1, ah2, ah3, bl2, bl3);
                MMA16816(d[2 * j2 + 1], al0, al1, al2, al3, bh2, bh3);
            }
        }
        __syncthreads();
    }

    const int r0 = w * 16 + (lane >> 2);
    const int gr0 = rowBase + r0, gr1 = gr0 + 8;
    const int cbase = (lane & 3) * 2;
    float ss0 = 0.f, ss1 = 0.f;
    #pragma unroll
    for (int j = 0; j < 4; ++j) {
        int c = j * 8 + cbase;
        float bb0 = b1[c], bb1 = b1[c + 1];
        float o0 = fmaxf(d[j][0] + bb0, 0.f), o1 = fmaxf(d[j][1] + bb1, 0.f);
        float o2 = fmaxf(d[j][2] + bb0, 0.f), o3 = fmaxf(d[j][3] + bb1, 0.f);
        ss0 += o0 * o0 + o1 * o1;
        ss1 += o2 * o2 + o3 * o3;
        if (gr0 < n) *(float2*)(g_h1 + (size_t)gr0 * HID + c) = make_float2(o0, o1);
        if (gr1 < n) *(float2*)(g_h1 + (size_t)gr1 * HID + c) = make_float2(o2, o3);
    }
    ss0 += __shfl_xor_sync(0xffffffffu, ss0, 1);
    ss0 += __shfl_xor_sync(0xffffffffu, ss0, 2);
    ss1 += __shfl_xor_sync(0xffffffffu, ss1, 1);
    ss1 += __shfl_xor_sync(0xffffffffu, ss1, 2);
    if ((lane & 3) == 0) {
        if (gr0 < n) g_invA[gr0] = rsqrtf(ss0 + 1e-12f);
        if (gr1 < n) g_invA[gr1] = rsqrtf(ss1 + 1e-12f);
    }
}

// ---------------- scans ----------------
__global__ void k_scan1(int n) {
    __shared__ int wsum[32];
    int i = blockIdx.x * 1024 + threadIdx.x;
    int lane = threadIdx.x & 31, warp = threadIdx.x >> 5;
    int v = (i < n) ? g_deg[i] : 0;
    int s = v;
    #pragma unroll
    for (int o = 1; o < 32; o <<= 1) {
        int t = __shfl_up_sync(0xffffffffu, s, o);
        if (lane >= o) s += t;
    }
    if (lane == 31) wsum[warp] = s;
    __syncthreads();
    if (warp == 0) {
        int w = wsum[lane];
        #pragma unroll
        for (int o = 1; o < 32; o <<= 1) {
            int t = __shfl_up_sync(0xffffffffu, w, o);
            if (lane >= o) w += t;
        }
        wsum[lane] = w;
    }
    __syncthreads();
    int pre = (warp > 0) ? wsum[warp - 1] : 0;
    s += pre;
    if (i < n) g_rowptr[i + 1] = s;
    if (threadIdx.x == 1023) g_bsum[blockIdx.x] = s;
}

__global__ void k_scan2(int nb) {
    __shared__ int s[256];
    int t = threadIdx.x;
    int v = (t < nb) ? g_bsum[t] : 0;
    s[t] = v;
    __syncthreads();
    for (int off = 1; off < 256; off <<= 1) {
        int u = (t >= off) ? s[t - off] : 0;
        __syncthreads();
        s[t] += u;
        __syncthreads();
    }
    if (t < nb) g_bsum[t] = (t == 0) ? 0 : s[t - 1];
}

__global__ void k_scan3c(int n) {
    int i = blockIdx.x * blockDim.x + threadIdx.x;
    if (i == 0) { g_rowptr[0] = 0; g_cursor[0] = 0; }
    if (i < n) {
        int f = g_rowptr[i + 1] + g_bsum[i >> 10];
        g_rowptr[i + 1] = f;
        if (i + 1 < n) g_cursor[i + 1] = f;
    }
}

__global__ void k_scatter(const void* __restrict__ ei, int E) {
    for (int e = blockIdx.x * blockDim.x + threadIdx.x; e < E;
         e += gridDim.x * blockDim.x) {
        int src = edge_at(ei, e);
        int dst = g_dst32[e];
        int p = atomicAdd(&g_cursor[dst], 1);
        g_col[p] = src;
    }
}

// ---------------- AGNN conv: warp per dst, 4 edge-slots x 8 feat-lanes ----------------
__global__ __launch_bounds__(256) void k_conv(int n, const float* __restrict__ beta_ptr,
                                              int dir, int write_norm) {
    const float* hin  = dir ? g_h2 : g_h1;
    float* hout       = dir ? g_h1 : g_h2;
    const float* ninv = dir ? g_invB : g_invA;

    int wid = (blockIdx.x * blockDim.x + threadIdx.x) >> 5;
    if (wid >= n) return;
    int lane = threadIdx.x & 31;
    int sub = lane >> 3;
    int fid = lane & 7;

    float beta = beta_ptr ? *beta_ptr : 1.0f;
    int dst = wid;
    float4 hd = *(const float4*)(hin + (size_t)dst * HID + fid * 4);
    float cb = beta * ninv[dst];
    int s = g_rowptr[dst], e = g_rowptr[dst + 1];

    float ax = 0.f, ay = 0.f, az = 0.f, aw = 0.f, ssum = 0.f;
    int nit = (e - s + 3) >> 2;
    for (int it = 0; it < nit; ++it) {
        int p = s + it * 4 + sub;
        bool valid = p < e;
        int src = valid ? g_col[p] : dst;
        float4 hs = *(const float4*)(hin + (size_t)src * HID + fid * 4);
        float invs = ninv[src];
        float d = hs.x * hd.x + hs.y * hd.y + hs.z * hd.z + hs.w * hd.w;
        d += __shfl_xor_sync(0xffffffffu, d, 1);
        d += __shfl_xor_sync(0xffffffffu, d, 2);
        d += __shfl_xor_sync(0xffffffffu, d, 4);
        float w = valid ? __expf(cb * invs * d) : 0.f;
        ax = fmaf(w, hs.x, ax);
        ay = fmaf(w, hs.y, ay);
        az = fmaf(w, hs.z, az);
        aw = fmaf(w, hs.w, aw);
        ssum += w;
    }
    ax += __shfl_xor_sync(0xffffffffu, ax, 8);  ax += __shfl_xor_sync(0xffffffffu, ax, 16);
    ay += __shfl_xor_sync(0xffffffffu, ay, 8);  ay += __shfl_xor_sync(0xffffffffu, ay, 16);
    az += __shfl_xor_sync(0xffffffffu, az, 8);  az += __shfl_xor_sync(0xffffffffu, az, 16);
    aw += __shfl_xor_sync(0xffffffffu, aw, 8);  aw += __shfl_xor_sync(0xffffffffu, aw, 16);
    ssum += __shfl_xor_sync(0xffffffffu, ssum, 8);
    ssum += __shfl_xor_sync(0xffffffffu, ssum, 16);

    float r = 1.f / (ssum + 1e-16f);
    float4 o = make_float4(ax * r, ay * r, az * r, aw * r);

    if (write_norm) {
        float ss = o.x * o.x + o.y * o.y + o.z * o.z + o.w * o.w;
        ss += __shfl_xor_sync(0xffffffffu, ss, 1);
        ss += __shfl_xor_sync(0xffffffffu, ss, 2);
        ss += __shfl_xor_sync(0xffffffffu, ss, 4);
        if (lane == 0) g_invB[dst] = rsqrtf(ss + 1e-12f);
    }
    if (sub == 0)
        *(float4*)(hout + (size_t)dst * HID + fid * 4) = o;
}

// ---------------- GEMM2: out = h1 @ W2 + b2 ----------------
__global__ __launch_bounds__(128) void k_gemm2(const float* __restrict__ W2,
                                               const float* __restrict__ b2,
                                               float* __restrict__ out, int n) {
    __shared__ __align__(16) float ws[HID * NCLS];
    __shared__ float bs[NCLS];
    for (int i = threadIdx.x; i < HID * NCLS; i += 128) ws[i] = W2[i];
    if (threadIdx.x < NCLS) bs[threadIdx.x] = b2[threadIdx.x];
    __syncthreads();

    int node = blockIdx.x * blockDim.x + threadIdx.x;
    if (node >= n) return;

    float xr[HID];
    #pragma unroll
    for (int q = 0; q < 8; ++q) {
        float4 v = *(const float4*)(g_h1 + (size_t)node * HID + q * 4);
        xr[q * 4 + 0] = v.x; xr[q * 4 + 1] = v.y;
        xr[q * 4 + 2] = v.z; xr[q * 4 + 3] = v.w;
    }
    float acc[NCLS];
    #pragma unroll
    for (int c = 0; c < NCLS; ++c) acc[c] = bs[c];
    #pragma unroll 8
    for (int k = 0; k < HID; ++k) {
        float xv = xr[k];
        #pragma unroll
        for (int c = 0; c < NCLS; ++c) acc[c] = fmaf(xv, ws[k * NCLS + c], acc[c]);
    }
    #pragma unroll
    for (int q = 0; q < 10; ++q) {
        float4 o = make_float4(acc[q * 4], acc[q * 4 + 1], acc[q * 4 + 2], acc[q * 4 + 3]);
        *(float4*)(out + (size_t)node * NCLS + q * 4) = o;
    }
}

// ---------------- host ----------------
extern "C" void kernel_launch(void* const* d_in, const int* in_sizes, int n_in,
                              void* d_out, int out_size) {
    const float* x = nullptr;
    const float* W1 = nullptr;
    const float* b1 = nullptr;
    const float* W2 = nullptr;
    const float* b2 = nullptr;
    const float* beta2 = nullptr;
    const void* ei = nullptr;
    int xsz = 0, esz = 0;

    for (int i = 0; i < n_in; ++i) {
        int sz = in_sizes[i];
        if (sz == NMAX * KIN)            { x = (const float*)d_in[i]; xsz = sz; }
        else if (sz == KIN * HID)        W1 = (const float*)d_in[i];
        else if (sz == HID)              b1 = (const float*)d_in[i];
        else if (sz == HID * NCLS)       W2 = (const float*)d_in[i];
        else if (sz == NCLS)             b2 = (const float*)d_in[i];
        else if (sz == 1)                beta2 = (const float*)d_in[i];
        else if (sz == 2 * EMAX)         { ei = d_in[i]; esz = sz; }
    }
    if (!x || !W1 || !b1 || !W2 || !b2 || !beta2 || !ei) {
        x = (const float*)d_in[0]; xsz = in_sizes[0];
        W1 = (const float*)d_in[1]; b1 = (const float*)d_in[2];
        W2 = (const float*)d_in[3]; b2 = (const float*)d_in[4];
        beta2 = (const float*)d_in[5];
        ei = d_in[6]; esz = in_sizes[6];
    }

    const int n = xsz / KIN;      // 100000
    const int E = esz / 2;        // 1700000
    const int nb = (n + 1023) / 1024;
    const int nbG = (n + 127) / 128;

    k_init<<<(n + 255) / 256, 256>>>((const int*)ei, n);
    k_g1h<<<nbG + NB_HIST, 256>>>(x, W1, b1, n, nbG, ei, E);   // gemm1 || hist

    k_scan1<<<nb, 1024>>>(n);
    k_scan2<<<1, 256>>>(nb);
    k_scan3c<<<nb, 1024>>>(n);
    k_scatter<<<2048, 256>>>(ei, E);

    k_conv<<<(n + 7) / 8, 256>>>(n, nullptr, 0, 1);   // prop1: beta=1, h1->h2, write g_invB
    k_conv<<<(n + 7) / 8, 256>>>(n, beta2, 1, 0);     // prop2: beta=beta2, h2->h1

    k_gemm2<<<(n + 127) / 128, 128>>>(W2, b2, (float*)d_out, n);
    (void)out_size;
}